// round 9
// baseline (speedup 1.0000x reference)
#include <cuda_runtime.h>
#include <math.h>

// Problem constants
#define BB   8
#define LL   2048
#define DD   1024
#define TOK  (BB*LL)            // 16384
#define SROWS 2049              // S_max + 1

// ---------------- scratch (no allocations allowed) ----------------
__device__ float g_partial[8 * TOK];   // per col-group partial logits
__device__ int   g_hard[TOK];          // hard boundary 0/1
__device__ int   g_cum[TOK];           // inclusive cumsum of hard
__device__ int   g_start[BB * 2050];   // segment start indices per row
__device__ int   g_nseg[BB];           // number of non-empty segments per row

// ---------------- f32x2 helpers (Blackwell packed fp32) ----------------
__device__ __forceinline__ unsigned long long dupf(float v) {
    unsigned long long r;
    asm("mov.b64 %0, {%1, %1};" : "=l"(r) : "f"(v));
    return r;
}
__device__ __forceinline__ void ffma2(unsigned long long& acc,
                                      unsigned long long a,
                                      unsigned long long b) {
    asm("fma.rn.f32x2 %0, %1, %2, %0;" : "+l"(acc) : "l"(a), "l"(b));
}
__device__ __forceinline__ float2 unpack2(unsigned long long v) {
    float2 f;
    asm("mov.b64 {%0, %1}, %2;" : "=f"(f.x), "=f"(f.y) : "l"(v));
    return f;
}

// ---------------------------------------------------------------------
// Kernel 1: fused GEMM  partial[cg][t] = sum_{j in colgrp} relu(x@W1 + b1)[t,j] * W2[j]
// grid (128 token tiles, 8 col groups), 256 threads, 128x128 tile, K-chunk 16.
// ---------------------------------------------------------------------
__global__ __launch_bounds__(256, 2)
void gemm_logits_kernel(const float* __restrict__ x,
                        const float* __restrict__ W1,
                        const float* __restrict__ b1,
                        const float* __restrict__ W2) {
    __shared__ float As[16][132];   // transposed A tile (padded)
    __shared__ float Bs[16][128];
    __shared__ float b1s[128];
    __shared__ float w2s[128];

    const int tid = threadIdx.x;
    const int t0  = blockIdx.x * 128;
    const int j0  = blockIdx.y * 128;
    const int tx  = tid & 15;
    const int ty  = tid >> 4;
    const int row_base = ty * 8;
    const int col_base = tx * 8;

    if (tid < 128) { b1s[tid] = b1[j0 + tid]; w2s[tid] = W2[j0 + tid]; }

    // global load mapping
    const int ar0 = tid >> 2;          // token row within tile (0..63)
    const int akp = tid & 3;           // k float4 slot (0..3)
    const float* aP = x + (size_t)(t0 + ar0) * DD + akp * 4;
    const int bk0 = tid >> 5;          // k row (0..7)
    const int bj  = (tid & 31) * 4;    // col offset
    const float* bP = W1 + (size_t)bk0 * DD + j0 + bj;

    unsigned long long acc[8][4];
#pragma unroll
    for (int i = 0; i < 8; ++i)
#pragma unroll
        for (int p = 0; p < 4; ++p) acc[i][p] = 0ull;

    // prefetch + store chunk 0
    float4 aR0 = *(const float4*)(aP);
    float4 aR1 = *(const float4*)(aP + 64 * DD);
    float4 bR0 = *(const float4*)(bP);
    float4 bR1 = *(const float4*)(bP + 8 * DD);

    {
        const int kb = akp * 4;
        As[kb + 0][ar0] = aR0.x; As[kb + 1][ar0] = aR0.y;
        As[kb + 2][ar0] = aR0.z; As[kb + 3][ar0] = aR0.w;
        As[kb + 0][ar0 + 64] = aR1.x; As[kb + 1][ar0 + 64] = aR1.y;
        As[kb + 2][ar0 + 64] = aR1.z; As[kb + 3][ar0 + 64] = aR1.w;
        *(float4*)&Bs[bk0][bj]     = bR0;
        *(float4*)&Bs[bk0 + 8][bj] = bR1;
    }
    __syncthreads();

    for (int kc = 0; kc < 64; ++kc) {
        if (kc < 63) {
            const int kn = (kc + 1) * 16;
            aR0 = *(const float4*)(aP + kn);
            aR1 = *(const float4*)(aP + 64 * DD + kn);
            bR0 = *(const float4*)(bP + (size_t)kn * DD);
            bR1 = *(const float4*)(bP + (size_t)(kn + 8) * DD);
        }
#pragma unroll
        for (int kk = 0; kk < 16; ++kk) {
            float4 a01 = *(const float4*)&As[kk][row_base];
            float4 a23 = *(const float4*)&As[kk][row_base + 4];
            ulonglong2 bb0 = *(const ulonglong2*)&Bs[kk][col_base];
            ulonglong2 bb1 = *(const ulonglong2*)&Bs[kk][col_base + 4];
            unsigned long long B2[4] = { bb0.x, bb0.y, bb1.x, bb1.y };
            float av[8] = { a01.x, a01.y, a01.z, a01.w,
                            a23.x, a23.y, a23.z, a23.w };
#pragma unroll
            for (int i = 0; i < 8; ++i) {
                unsigned long long a2 = dupf(av[i]);
#pragma unroll
                for (int p = 0; p < 4; ++p) ffma2(acc[i][p], a2, B2[p]);
            }
        }
        if (kc < 63) {
            __syncthreads();
            const int kb = akp * 4;
            As[kb + 0][ar0] = aR0.x; As[kb + 1][ar0] = aR0.y;
            As[kb + 2][ar0] = aR0.z; As[kb + 3][ar0] = aR0.w;
            As[kb + 0][ar0 + 64] = aR1.x; As[kb + 1][ar0 + 64] = aR1.y;
            As[kb + 2][ar0 + 64] = aR1.z; As[kb + 3][ar0 + 64] = aR1.w;
            *(float4*)&Bs[bk0][bj]     = bR0;
            *(float4*)&Bs[bk0 + 8][bj] = bR1;
            __syncthreads();
        }
    }

    __syncthreads();  // done reading As/Bs; reuse As as reduction buffer

    // epilogue: relu + dot with W2, per-thread partial over its 8 cols
    float lg[8];
#pragma unroll
    for (int i = 0; i < 8; ++i) lg[i] = 0.0f;
#pragma unroll
    for (int i = 0; i < 8; ++i) {
#pragma unroll
        for (int p = 0; p < 4; ++p) {
            float2 c = unpack2(acc[i][p]);
            const int jc = col_base + p * 2;
            float h0 = fmaxf(c.x + b1s[jc], 0.0f);
            float h1 = fmaxf(c.y + b1s[jc + 1], 0.0f);
            lg[i] += h0 * w2s[jc] + h1 * w2s[jc + 1];
        }
    }

    float* red = &As[0][0];  // 128*16 = 2048 <= 16*132
#pragma unroll
    for (int i = 0; i < 8; ++i) red[(row_base + i) * 16 + tx] = lg[i];
    __syncthreads();

    if (tid < 128) {
        float s = 0.0f;
#pragma unroll
        for (int t = 0; t < 16; ++t) s += red[tid * 16 + t];
        g_partial[(size_t)blockIdx.y * TOK + t0 + tid] = s;
    }
}

// ---------------------------------------------------------------------
// Kernel 2: combine partials + gumbel noise -> hard boundaries
// ---------------------------------------------------------------------
__global__ void boundary_kernel(const float* __restrict__ noise,
                                const float* __restrict__ b2) {
    const int i = blockIdx.x * 256 + threadIdx.x;
    float s = b2[0];
#pragma unroll
    for (int cg = 0; cg < 8; ++cg) s += g_partial[cg * TOK + i];
    float u = noise[i];
    u = fminf(fmaxf(u, 1e-6f), 1.0f - 1e-6f);
    float z = s + logf(u) - log1pf(-u);
    float soft = 1.0f / (1.0f + expf(-z));
    g_hard[i] = (soft > 0.5f) ? 1 : 0;
}

// ---------------------------------------------------------------------
// Kernel 3: per-row prefix scan, segment starts, inclusive cumsum
// one block per batch row, 256 threads x 8 elements
// ---------------------------------------------------------------------
__global__ void scan_kernel() {
    const int b = blockIdx.x;
    const int tid = threadIdx.x;
    __shared__ int e_sh[LL];
    __shared__ int ts[256];

    const int base = tid * 8;
    int h[8];
    int sum = 0;
#pragma unroll
    for (int j = 0; j < 8; ++j) { h[j] = g_hard[b * LL + base + j]; sum += h[j]; }
    ts[tid] = sum;
    __syncthreads();

    // inclusive Hillis-Steele scan over 256 thread sums
    for (int off = 1; off < 256; off <<= 1) {
        int v = (tid >= off) ? ts[tid - off] : 0;
        __syncthreads();
        ts[tid] += v;
        __syncthreads();
    }
    int run = ts[tid] - sum;  // exclusive base for this chunk

#pragma unroll
    for (int j = 0; j < 8; ++j) {
        e_sh[base + j] = run;                       // exclusive prefix (segment id, downsample)
        g_cum[b * LL + base + j] = run + h[j];      // inclusive cumsum (upsample gather idx)
        run += h[j];
    }
    __syncthreads();

#pragma unroll
    for (int j = 0; j < 8; ++j) {
        const int l = base + j;
        const int el = e_sh[l];
        if (l == 0 || e_sh[l - 1] != el) g_start[b * 2050 + el] = l;
    }
    if (tid == 255) {
        const int ns = e_sh[LL - 1] + 1;
        g_nseg[b] = ns;
        g_start[b * 2050 + ns] = LL;  // sentinel end
    }
}

// ---------------------------------------------------------------------
// Kernel 4: shortened = [null_group ; segment means ; zeros]
// grid (2049, 8), 256 threads -> one float4 per thread
// ---------------------------------------------------------------------
__global__ void shortened_kernel(const float* __restrict__ x,
                                 const float* __restrict__ null_group,
                                 float* __restrict__ outS) {
    const int b = blockIdx.y;
    const int srow = blockIdx.x;
    const int tid = threadIdx.x;
    float4* op = (float4*)(outS + ((size_t)b * SROWS + srow) * DD) + tid;

    if (srow == 0) { *op = ((const float4*)null_group)[tid]; return; }
    const int s = srow - 1;
    if (s >= g_nseg[b]) { *op = make_float4(0.f, 0.f, 0.f, 0.f); return; }

    const int l0 = g_start[b * 2050 + s];
    const int l1 = g_start[b * 2050 + s + 1];
    float4 acc = make_float4(0.f, 0.f, 0.f, 0.f);
    const float4* xp = (const float4*)(x + ((size_t)b * LL + l0) * DD) + tid;
    for (int l = l0; l < l1; ++l) {
        float4 v = *xp;
        acc.x += v.x; acc.y += v.y; acc.z += v.z; acc.w += v.w;
        xp += DD / 4;
    }
    const float inv = 1.0f / ((float)(l1 - l0) + 1e-9f);
    acc.x *= inv; acc.y *= inv; acc.z *= inv; acc.w *= inv;
    *op = acc;
}

// ---------------------------------------------------------------------
// Kernel 5: upsampled[b,l,:] = shortened[b, cumsum(l), :]   (scale == 1.0f exactly)
// ---------------------------------------------------------------------
__global__ void upsample_kernel(const float* __restrict__ outS,
                                float* __restrict__ outU) {
    const int b = blockIdx.y;
    const int l = blockIdx.x;
    const int tid = threadIdx.x;
    const int c = g_cum[b * LL + l];
    const float4* sp = (const float4*)(outS + ((size_t)b * SROWS + c) * DD) + tid;
    float4* up = (float4*)(outU + ((size_t)b * LL + l) * DD) + tid;
    *up = *sp;
}

// ---------------------------------------------------------------------
// Kernel 6: binomial consistency loss (scalar)
// ---------------------------------------------------------------------
__global__ void loss_kernel(float* __restrict__ outLoss) {
    if (threadIdx.x == 0) {
        const double Lf = 2048.0;
        const double lgL = lgamma(2049.0);
        const double lp = log(0.25);
        const double l1p = log(0.75);
        double s = 0.0;
        for (int b = 0; b < BB; ++b) {
            double k = (double)g_cum[b * LL + LL - 1];
            double logp = lgL - lgamma(k + 1.0) - lgamma(Lf - k + 1.0)
                        + k * lp + (Lf - k) * l1p;
            s += logp;
        }
        outLoss[0] = (float)(-(s / 8.0) / 2048.0);
    }
}

// ---------------------------------------------------------------------
extern "C" void kernel_launch(void* const* d_in, const int* in_sizes, int n_in,
                              void* d_out, int out_size) {
    (void)in_sizes; (void)n_in; (void)out_size;

    const float* x          = (const float*)d_in[0];
    const float* noise      = (const float*)d_in[1];
    const float* W1         = (const float*)d_in[2];
    const float* b1         = (const float*)d_in[3];
    const float* W2         = (const float*)d_in[4];
    const float* b2         = (const float*)d_in[5];
    const float* null_group = (const float*)d_in[6];

    float* out  = (float*)d_out;
    float* outS = out;                                     // [8, 2049, 1024]
    float* outU = outS + (size_t)BB * SROWS * DD;          // [8, 2048, 1024]
    float* outL = outU + (size_t)BB * LL * DD;             // scalar

    gemm_logits_kernel<<<dim3(TOK / 128, DD / 128), 256>>>(x, W1, b1, W2);
    boundary_kernel<<<TOK / 256, 256>>>(noise, b2);
    scan_kernel<<<BB, 256>>>();
    shortened_kernel<<<dim3(SROWS, BB), 256>>>(x, null_group, outS);
    upsample_kernel<<<dim3(LL, BB), 256>>>(outS, outU);
    loss_kernel<<<1, 32>>>(outL);
}

// round 10
// speedup vs baseline: 1.0034x; 1.0034x over previous
#include <cuda_runtime.h>
#include <math.h>

// Problem constants
#define BB   8
#define LL   2048
#define DD   1024
#define TOK  (BB*LL)            // 16384
#define SROWS 2049              // S_max + 1

// ---------------- scratch (no allocations allowed) ----------------
__device__ float g_partial[8 * TOK];   // per col-group partial logits
__device__ int   g_hard[TOK];          // hard boundary 0/1
__device__ int   g_cum[TOK];           // inclusive cumsum of hard
__device__ int   g_start[BB * 2050];   // segment start indices per row
__device__ int   g_nseg[BB];           // number of non-empty segments per row

// ---------------- f32x2 helpers (Blackwell packed fp32) ----------------
__device__ __forceinline__ unsigned long long dupf(float v) {
    unsigned long long r;
    asm("mov.b64 %0, {%1, %1};" : "=l"(r) : "f"(v));
    return r;
}
__device__ __forceinline__ void ffma2(unsigned long long& acc,
                                      unsigned long long a,
                                      unsigned long long b) {
    asm("fma.rn.f32x2 %0, %1, %2, %0;" : "+l"(acc) : "l"(a), "l"(b));
}
__device__ __forceinline__ float2 unpack2(unsigned long long v) {
    float2 f;
    asm("mov.b64 {%0, %1}, %2;" : "=f"(f.x), "=f"(f.y) : "l"(v));
    return f;
}

// ---------------------------------------------------------------------
// Kernel 1: fused GEMM  partial[cg][t] = sum_{j in colgrp} relu(x@W1 + b1)[t,j] * W2[j]
// grid (128 token tiles, 8 col groups), 256 threads, 128x128 tile, K-chunk 16.
// ---------------------------------------------------------------------
__global__ __launch_bounds__(256, 2)
void gemm_logits_kernel(const float* __restrict__ x,
                        const float* __restrict__ W1,
                        const float* __restrict__ b1,
                        const float* __restrict__ W2) {
    __shared__ float As[16][132];   // transposed A tile (padded)
    __shared__ float Bs[16][128];
    __shared__ float b1s[128];
    __shared__ float w2s[128];

    const int tid = threadIdx.x;
    const int t0  = blockIdx.x * 128;
    const int j0  = blockIdx.y * 128;
    const int tx  = tid & 15;
    const int ty  = tid >> 4;
    const int row_base = ty * 8;
    const int col_base = tx * 8;

    if (tid < 128) { b1s[tid] = b1[j0 + tid]; w2s[tid] = W2[j0 + tid]; }

    // global load mapping
    const int ar0 = tid >> 2;          // token row within tile (0..63)
    const int akp = tid & 3;           // k float4 slot (0..3)
    const float* aP = x + (size_t)(t0 + ar0) * DD + akp * 4;
    const int bk0 = tid >> 5;          // k row (0..7)
    const int bj  = (tid & 31) * 4;    // col offset
    const float* bP = W1 + (size_t)bk0 * DD + j0 + bj;

    unsigned long long acc[8][4];
#pragma unroll
    for (int i = 0; i < 8; ++i)
#pragma unroll
        for (int p = 0; p < 4; ++p) acc[i][p] = 0ull;

    // prefetch + store chunk 0
    float4 aR0 = *(const float4*)(aP);
    float4 aR1 = *(const float4*)(aP + 64 * DD);
    float4 bR0 = *(const float4*)(bP);
    float4 bR1 = *(const float4*)(bP + 8 * DD);

    {
        const int kb = akp * 4;
        As[kb + 0][ar0] = aR0.x; As[kb + 1][ar0] = aR0.y;
        As[kb + 2][ar0] = aR0.z; As[kb + 3][ar0] = aR0.w;
        As[kb + 0][ar0 + 64] = aR1.x; As[kb + 1][ar0 + 64] = aR1.y;
        As[kb + 2][ar0 + 64] = aR1.z; As[kb + 3][ar0 + 64] = aR1.w;
        *(float4*)&Bs[bk0][bj]     = bR0;
        *(float4*)&Bs[bk0 + 8][bj] = bR1;
    }
    __syncthreads();

    for (int kc = 0; kc < 64; ++kc) {
        if (kc < 63) {
            const int kn = (kc + 1) * 16;
            aR0 = *(const float4*)(aP + kn);
            aR1 = *(const float4*)(aP + 64 * DD + kn);
            bR0 = *(const float4*)(bP + (size_t)kn * DD);
            bR1 = *(const float4*)(bP + (size_t)(kn + 8) * DD);
        }
#pragma unroll
        for (int kk = 0; kk < 16; ++kk) {
            float4 a01 = *(const float4*)&As[kk][row_base];
            float4 a23 = *(const float4*)&As[kk][row_base + 4];
            ulonglong2 bb0 = *(const ulonglong2*)&Bs[kk][col_base];
            ulonglong2 bb1 = *(const ulonglong2*)&Bs[kk][col_base + 4];
            unsigned long long B2[4] = { bb0.x, bb0.y, bb1.x, bb1.y };
            float av[8] = { a01.x, a01.y, a01.z, a01.w,
                            a23.x, a23.y, a23.z, a23.w };
#pragma unroll
            for (int i = 0; i < 8; ++i) {
                unsigned long long a2 = dupf(av[i]);
#pragma unroll
                for (int p = 0; p < 4; ++p) ffma2(acc[i][p], a2, B2[p]);
            }
        }
        if (kc < 63) {
            __syncthreads();
            const int kb = akp * 4;
            As[kb + 0][ar0] = aR0.x; As[kb + 1][ar0] = aR0.y;
            As[kb + 2][ar0] = aR0.z; As[kb + 3][ar0] = aR0.w;
            As[kb + 0][ar0 + 64] = aR1.x; As[kb + 1][ar0 + 64] = aR1.y;
            As[kb + 2][ar0 + 64] = aR1.z; As[kb + 3][ar0 + 64] = aR1.w;
            *(float4*)&Bs[bk0][bj]     = bR0;
            *(float4*)&Bs[bk0 + 8][bj] = bR1;
            __syncthreads();
        }
    }

    __syncthreads();  // done reading As/Bs; reuse As as reduction buffer

    // epilogue: relu + dot with W2, per-thread partial over its 8 cols
    float lg[8];
#pragma unroll
    for (int i = 0; i < 8; ++i) lg[i] = 0.0f;
#pragma unroll
    for (int i = 0; i < 8; ++i) {
#pragma unroll
        for (int p = 0; p < 4; ++p) {
            float2 c = unpack2(acc[i][p]);
            const int jc = col_base + p * 2;
            float h0 = fmaxf(c.x + b1s[jc], 0.0f);
            float h1 = fmaxf(c.y + b1s[jc + 1], 0.0f);
            lg[i] += h0 * w2s[jc] + h1 * w2s[jc + 1];
        }
    }

    float* red = &As[0][0];  // 128*16 = 2048 <= 16*132
#pragma unroll
    for (int i = 0; i < 8; ++i) red[(row_base + i) * 16 + tx] = lg[i];
    __syncthreads();

    if (tid < 128) {
        float s = 0.0f;
#pragma unroll
        for (int t = 0; t < 16; ++t) s += red[tid * 16 + t];
        g_partial[(size_t)blockIdx.y * TOK + t0 + tid] = s;
    }
}

// ---------------------------------------------------------------------
// Kernel 2: combine partials + gumbel noise -> hard boundaries
// ---------------------------------------------------------------------
__global__ void boundary_kernel(const float* __restrict__ noise,
                                const float* __restrict__ b2) {
    const int i = blockIdx.x * 256 + threadIdx.x;
    float s = b2[0];
#pragma unroll
    for (int cg = 0; cg < 8; ++cg) s += g_partial[cg * TOK + i];
    float u = noise[i];
    u = fminf(fmaxf(u, 1e-6f), 1.0f - 1e-6f);
    float z = s + logf(u) - log1pf(-u);
    float soft = 1.0f / (1.0f + expf(-z));
    g_hard[i] = (soft > 0.5f) ? 1 : 0;
}

// ---------------------------------------------------------------------
// Kernel 3: per-row prefix scan, segment starts, inclusive cumsum
// one block per batch row, 256 threads x 8 elements
// ---------------------------------------------------------------------
__global__ void scan_kernel() {
    const int b = blockIdx.x;
    const int tid = threadIdx.x;
    __shared__ int e_sh[LL];
    __shared__ int ts[256];

    const int base = tid * 8;
    int h[8];
    int sum = 0;
#pragma unroll
    for (int j = 0; j < 8; ++j) { h[j] = g_hard[b * LL + base + j]; sum += h[j]; }
    ts[tid] = sum;
    __syncthreads();

    // inclusive Hillis-Steele scan over 256 thread sums
    for (int off = 1; off < 256; off <<= 1) {
        int v = (tid >= off) ? ts[tid - off] : 0;
        __syncthreads();
        ts[tid] += v;
        __syncthreads();
    }
    int run = ts[tid] - sum;  // exclusive base for this chunk

#pragma unroll
    for (int j = 0; j < 8; ++j) {
        e_sh[base + j] = run;                       // exclusive prefix (segment id, downsample)
        g_cum[b * LL + base + j] = run + h[j];      // inclusive cumsum (upsample gather idx)
        run += h[j];
    }
    __syncthreads();

#pragma unroll
    for (int j = 0; j < 8; ++j) {
        const int l = base + j;
        const int el = e_sh[l];
        if (l == 0 || e_sh[l - 1] != el) g_start[b * 2050 + el] = l;
    }
    if (tid == 255) {
        const int ns = e_sh[LL - 1] + 1;
        g_nseg[b] = ns;
        g_start[b * 2050 + ns] = LL;  // sentinel end
    }
}

// ---------------------------------------------------------------------
// Kernel 4: shortened = [null_group ; segment means ; zeros]
// grid (2049, 8), 256 threads -> one float4 per thread
// ---------------------------------------------------------------------
__global__ void shortened_kernel(const float* __restrict__ x,
                                 const float* __restrict__ null_group,
                                 float* __restrict__ outS) {
    const int b = blockIdx.y;
    const int srow = blockIdx.x;
    const int tid = threadIdx.x;
    float4* op = (float4*)(outS + ((size_t)b * SROWS + srow) * DD) + tid;

    if (srow == 0) { *op = ((const float4*)null_group)[tid]; return; }
    const int s = srow - 1;
    if (s >= g_nseg[b]) { *op = make_float4(0.f, 0.f, 0.f, 0.f); return; }

    const int l0 = g_start[b * 2050 + s];
    const int l1 = g_start[b * 2050 + s + 1];
    float4 acc = make_float4(0.f, 0.f, 0.f, 0.f);
    const float4* xp = (const float4*)(x + ((size_t)b * LL + l0) * DD) + tid;
    for (int l = l0; l < l1; ++l) {
        float4 v = *xp;
        acc.x += v.x; acc.y += v.y; acc.z += v.z; acc.w += v.w;
        xp += DD / 4;
    }
    const float inv = 1.0f / ((float)(l1 - l0) + 1e-9f);
    acc.x *= inv; acc.y *= inv; acc.z *= inv; acc.w *= inv;
    *op = acc;
}

// ---------------------------------------------------------------------
// Kernel 5: upsampled[b,l,:] = shortened[b, cumsum(l), :]   (scale == 1.0f exactly)
// ---------------------------------------------------------------------
__global__ void upsample_kernel(const float* __restrict__ outS,
                                float* __restrict__ outU) {
    const int b = blockIdx.y;
    const int l = blockIdx.x;
    const int tid = threadIdx.x;
    const int c = g_cum[b * LL + l];
    const float4* sp = (const float4*)(outS + ((size_t)b * SROWS + c) * DD) + tid;
    float4* up = (float4*)(outU + ((size_t)b * LL + l) * DD) + tid;
    *up = *sp;
}

// ---------------------------------------------------------------------
// Kernel 6: binomial consistency loss (scalar)
// ---------------------------------------------------------------------
__global__ void loss_kernel(float* __restrict__ outLoss) {
    if (threadIdx.x == 0) {
        const double Lf = 2048.0;
        const double lgL = lgamma(2049.0);
        const double lp = log(0.25);
        const double l1p = log(0.75);
        double s = 0.0;
        for (int b = 0; b < BB; ++b) {
            double k = (double)g_cum[b * LL + LL - 1];
            double logp = lgL - lgamma(k + 1.0) - lgamma(Lf - k + 1.0)
                        + k * lp + (Lf - k) * l1p;
            s += logp;
        }
        outLoss[0] = (float)(-(s / 8.0) / 2048.0);
    }
}

// ---------------------------------------------------------------------
extern "C" void kernel_launch(void* const* d_in, const int* in_sizes, int n_in,
                              void* d_out, int out_size) {
    (void)in_sizes; (void)n_in; (void)out_size;

    const float* x          = (const float*)d_in[0];
    const float* noise      = (const float*)d_in[1];
    const float* W1         = (const float*)d_in[2];
    const float* b1         = (const float*)d_in[3];
    const float* W2         = (const float*)d_in[4];
    const float* b2         = (const float*)d_in[5];
    const float* null_group = (const float*)d_in[6];

    float* out  = (float*)d_out;
    float* outS = out;                                     // [8, 2049, 1024]
    float* outU = outS + (size_t)BB * SROWS * DD;          // [8, 2048, 1024]
    float* outL = outU + (size_t)BB * LL * DD;             // scalar

    gemm_logits_kernel<<<dim3(TOK / 128, DD / 128), 256>>>(x, W1, b1, W2);
    boundary_kernel<<<TOK / 256, 256>>>(noise, b2);
    scan_kernel<<<BB, 256>>>();
    shortened_kernel<<<dim3(SROWS, BB), 256>>>(x, null_group, outS);
    upsample_kernel<<<dim3(LL, BB), 256>>>(outS, outU);
    loss_kernel<<<1, 32>>>(outL);
}

// round 14
// speedup vs baseline: 2.2324x; 2.2249x over previous
#include <cuda_runtime.h>
#include <cuda_fp16.h>
#include <stdint.h>
#include <math.h>

// Problem constants
#define BB   8
#define LL   2048
#define DD   1024
#define TOK  (BB*LL)            // 16384
#define SROWS 2049              // S_max + 1
#define MARGIN 8e-3f

// ---------------- scratch (no allocations allowed) ----------------
__device__ __half g_xh[(size_t)TOK * DD];   // x in fp16 (32MB)
__device__ __half g_wth[DD * DD];           // W1^T in fp16 (2MB)
__device__ float g_partial[8 * TOK];   // per col-group partial logits
__device__ int   g_hard[TOK];          // hard boundary 0/1
__device__ int   g_cum[TOK];           // inclusive cumsum of hard
__device__ int   g_start[BB * 2050];   // segment start indices per row
__device__ int   g_nseg[BB];           // number of non-empty segments per row
__device__ int   g_fixtok[TOK];        // marginal tokens to recompute exactly
__device__ int   g_fixcnt;

// ====================== PTX helpers ======================
__device__ __forceinline__ uint32_t cvta_smem(const void* p) {
    uint32_t a;
    asm("{ .reg .u64 t; cvta.to.shared.u64 t, %1; cvt.u32.u64 %0, t; }"
        : "=r"(a) : "l"(p));
    return a;
}
__device__ __forceinline__ void cp16(uint32_t dst, const void* src) {
    asm volatile("cp.async.cg.shared.global [%0], [%1], 16;"
                 :: "r"(dst), "l"(src) : "memory");
}
__device__ __forceinline__ void ldm_x4(uint32_t* r, uint32_t a) {
    asm volatile("ldmatrix.sync.aligned.m8n8.x4.shared.b16 {%0,%1,%2,%3}, [%4];"
                 : "=r"(r[0]), "=r"(r[1]), "=r"(r[2]), "=r"(r[3]) : "r"(a));
}
__device__ __forceinline__ void mma16816(float* c, const uint32_t* a,
                                         uint32_t b0, uint32_t b1) {
    asm volatile(
        "mma.sync.aligned.m16n8k16.row.col.f32.f16.f16.f32 "
        "{%0,%1,%2,%3}, {%4,%5,%6,%7}, {%8,%9}, {%0,%1,%2,%3};"
        : "+f"(c[0]), "+f"(c[1]), "+f"(c[2]), "+f"(c[3])
        : "r"(a[0]), "r"(a[1]), "r"(a[2]), "r"(a[3]), "r"(b0), "r"(b1));
}

// ---------------------------------------------------------------------
// Kernel 0a: convert x to fp16; zero fixup counter
// ---------------------------------------------------------------------
__global__ void conv_x_kernel(const float* __restrict__ x) {
    const size_t i = ((size_t)blockIdx.x * 256 + threadIdx.x) * 4;
    float4 v = *(const float4*)(x + i);
    __half2* p = (__half2*)(g_xh + i);
    p[0] = __floats2half2_rn(v.x, v.y);
    p[1] = __floats2half2_rn(v.z, v.w);
    if (blockIdx.x == 0 && threadIdx.x == 0) g_fixcnt = 0;
}

// ---------------------------------------------------------------------
// Kernel 0b: W1^T in fp16:  wth[n][k] = (half)W1[k][n]
// ---------------------------------------------------------------------
__global__ void transpose_kernel(const float* __restrict__ W1) {
    __shared__ float t[32][33];
    const int bx = blockIdx.x * 32;   // n base
    const int by = blockIdx.y * 32;   // k base
    const int tx = threadIdx.x, ty = threadIdx.y;
#pragma unroll
    for (int i = 0; i < 32; i += 8)
        t[ty + i][tx] = W1[(size_t)(by + ty + i) * DD + bx + tx];
    __syncthreads();
#pragma unroll
    for (int i = 0; i < 32; i += 8) {
        float v = t[tx][ty + i];               // = W1[by+tx][bx+ty+i]
        g_wth[(size_t)(bx + ty + i) * DD + by + tx] = __float2half_rn(v);
    }
}

// ---------------------------------------------------------------------
// Kernel 1: HMMA fp16 GEMM with fused relu+W2 epilogue.
// grid (128 token tiles, 8 col groups), 256 threads (8 warps, 2x4).
// CTA tile M=128, N=128, K chunks of 64; warp tile 64x32; mma m16n8k16.
// ---------------------------------------------------------------------
#define KC 64
#define STAGE_BYTES 32768          // A tile 16KB + B tile 16KB
#define GEMM_SMEM (4096 + 2 * STAGE_BYTES)

__global__ __launch_bounds__(256, 2)
void mma_logits_kernel(const float* __restrict__ b1g, const float* __restrict__ w2g) {
    extern __shared__ char smem[];
    float* b1s = (float*)smem;                 // 512B
    float* w2s = (float*)(smem + 512);         // 512B
    float* red = (float*)(smem + 1024);        // 4*128 floats = 2KB
    const uint32_t tiles_u = cvta_smem(smem + 4096);

    const int tid = threadIdx.x;
    const int wid = tid >> 5, lane = tid & 31;
    const int t0 = blockIdx.x * 128;
    const int j0 = blockIdx.y * 128;
    const int warp_m = wid & 1;    // 0..1  (64 rows each)
    const int warp_n = wid >> 1;   // 0..3  (32 cols each)

    if (tid < 128) { b1s[tid] = b1g[j0 + tid]; w2s[tid] = w2g[j0 + tid]; }

    // cp.async stage loader: 1024 16B-chunks per tile (A then B), XOR swizzle
    auto load_stage = [&](int c, int st) {
        const uint32_t base = tiles_u + st * STAGE_BYTES;
        const __half* aS = g_xh + (size_t)t0 * DD + c * KC;
        const __half* bS = g_wth + (size_t)j0 * DD + c * KC;
#pragma unroll
        for (int it = 0; it < 4; ++it) {
            const int idx = tid + it * 256;          // 0..1023
            const int row = idx >> 3, ch = idx & 7;  // 128 rows x 8 chunks
            const uint32_t off = (uint32_t)(row * 128 + ((ch ^ (row & 7)) << 4));
            cp16(base + off,         aS + (size_t)row * DD + ch * 8);
            cp16(base + 16384 + off, bS + (size_t)row * DD + ch * 8);
        }
        asm volatile("cp.async.commit_group;" ::: "memory");
    };

    float acc[4][4][4];
#pragma unroll
    for (int mt = 0; mt < 4; ++mt)
#pragma unroll
        for (int nt = 0; nt < 4; ++nt)
#pragma unroll
            for (int q = 0; q < 4; ++q) acc[mt][nt][q] = 0.0f;

    load_stage(0, 0);
    load_stage(1, 1);

    for (int c = 0; c < 16; ++c) {
        const int st = c & 1;
        if (c < 15) asm volatile("cp.async.wait_group 1;" ::: "memory");
        else        asm volatile("cp.async.wait_group 0;" ::: "memory");
        __syncthreads();

        const uint32_t aBase = tiles_u + st * STAGE_BYTES;
        const uint32_t bBase = aBase + 16384;

#pragma unroll
        for (int ks = 0; ks < 4; ++ks) {
            uint32_t af[4][4];
#pragma unroll
            for (int mt = 0; mt < 4; ++mt) {
                const int row = warp_m * 64 + mt * 16 + (lane & 15);
                const int ch = ks * 2 + (lane >> 4);
                ldm_x4(af[mt], aBase + row * 128 + (((ch ^ (row & 7)) << 4)));
            }
#pragma unroll
            for (int np = 0; np < 2; ++np) {     // covers n-tiles 2np, 2np+1
                const int grp = lane >> 3;
                const int n = warp_n * 32 + np * 16 + (grp & 1) * 8 + (lane & 7);
                const int ch = ks * 2 + (grp >> 1);
                uint32_t bf[4];
                ldm_x4(bf, bBase + n * 128 + (((ch ^ (n & 7)) << 4)));
#pragma unroll
                for (int mt = 0; mt < 4; ++mt) {
                    mma16816(acc[mt][np * 2],     af[mt], bf[0], bf[2]);
                    mma16816(acc[mt][np * 2 + 1], af[mt], bf[1], bf[3]);
                }
            }
        }
        __syncthreads();
        if (c + 2 < 16) load_stage(c + 2, st);
    }

    // ---- epilogue: lg[row] = sum_j relu(h + b1) * W2 over this 128-col group ----
    float accr[4][2];
#pragma unroll
    for (int mt = 0; mt < 4; ++mt) { accr[mt][0] = 0.f; accr[mt][1] = 0.f; }
#pragma unroll
    for (int nt = 0; nt < 4; ++nt) {
        const int cb = warp_n * 32 + nt * 8 + 2 * (lane & 3);
        const float w0 = w2s[cb], w1 = w2s[cb + 1];
        const float bb0 = b1s[cb], bb1 = b1s[cb + 1];
#pragma unroll
        for (int mt = 0; mt < 4; ++mt) {
            accr[mt][0] += fmaxf(acc[mt][nt][0] + bb0, 0.f) * w0
                         + fmaxf(acc[mt][nt][1] + bb1, 0.f) * w1;
            accr[mt][1] += fmaxf(acc[mt][nt][2] + bb0, 0.f) * w0
                         + fmaxf(acc[mt][nt][3] + bb1, 0.f) * w1;
        }
    }
#pragma unroll
    for (int mt = 0; mt < 4; ++mt) {
#pragma unroll
        for (int h = 0; h < 2; ++h) {
            float v = accr[mt][h];
            v += __shfl_xor_sync(0xFFFFFFFFu, v, 1);
            v += __shfl_xor_sync(0xFFFFFFFFu, v, 2);
            if ((lane & 3) == 0)
                red[warp_n * 128 + warp_m * 64 + mt * 16 + (lane >> 2) + h * 8] = v;
        }
    }
    __syncthreads();
    if (tid < 128) {
        const float s = red[tid] + red[128 + tid] + red[256 + tid] + red[384 + tid];
        g_partial[(size_t)blockIdx.y * TOK + t0 + tid] = s;
    }
}

// ---------------------------------------------------------------------
// Kernel 2: combine partials + gumbel noise -> hard boundaries (+fix list)
// ---------------------------------------------------------------------
__global__ void boundary_kernel(const float* __restrict__ noise,
                                const float* __restrict__ b2) {
    const int i = blockIdx.x * 256 + threadIdx.x;
    float s = b2[0];
#pragma unroll
    for (int cg = 0; cg < 8; ++cg) s += g_partial[cg * TOK + i];
    float u = noise[i];
    u = fminf(fmaxf(u, 1e-6f), 1.0f - 1e-6f);
    const float z = s + logf(u) - log1pf(-u);
    const float soft = 1.0f / (1.0f + expf(-z));
    g_hard[i] = (soft > 0.5f) ? 1 : 0;
    if (fabsf(z) < MARGIN) {
        const int p = atomicAdd(&g_fixcnt, 1);
        g_fixtok[p] = i;
    }
}

// ---------------------------------------------------------------------
// Kernel 2b: exact fp32 recompute of marginal tokens' logits
// ---------------------------------------------------------------------
__global__ void fixup_kernel(const float* __restrict__ x, const float* __restrict__ W1,
                             const float* __restrict__ b1, const float* __restrict__ W2,
                             const float* __restrict__ b2, const float* __restrict__ noise) {
    __shared__ float xs[DD];
    __shared__ float red[256];
    const int nt = g_fixcnt;
    for (int fi = blockIdx.x; fi < nt; fi += gridDim.x) {
        const int t = g_fixtok[fi];
        for (int k = threadIdx.x; k < DD; k += 256) xs[k] = x[(size_t)t * DD + k];
        __syncthreads();
        float acc[4] = {0.f, 0.f, 0.f, 0.f};
        for (int k = 0; k < DD; ++k) {
            const float xv = xs[k];
            const float* wr = W1 + (size_t)k * DD;
#pragma unroll
            for (int q = 0; q < 4; ++q) acc[q] += xv * wr[threadIdx.x + q * 256];
        }
        float lg = 0.0f;
#pragma unroll
        for (int q = 0; q < 4; ++q) {
            const int j = threadIdx.x + q * 256;
            lg += fmaxf(acc[q] + b1[j], 0.0f) * W2[j];
        }
        red[threadIdx.x] = lg;
        __syncthreads();
        for (int off = 128; off > 0; off >>= 1) {
            if (threadIdx.x < off) red[threadIdx.x] += red[threadIdx.x + off];
            __syncthreads();
        }
        if (threadIdx.x == 0) {
            const float s = red[0] + b2[0];
            float u = fminf(fmaxf(noise[t], 1e-6f), 1.0f - 1e-6f);
            const float z = s + logf(u) - log1pf(-u);
            const float soft = 1.0f / (1.0f + expf(-z));
            g_hard[t] = (soft > 0.5f) ? 1 : 0;
        }
        __syncthreads();
    }
}

// ---------------------------------------------------------------------
// Kernel 3: per-row prefix scan, segment starts, inclusive cumsum
// ---------------------------------------------------------------------
__global__ void scan_kernel() {
    const int b = blockIdx.x;
    const int tid = threadIdx.x;
    __shared__ int e_sh[LL];
    __shared__ int ts[256];

    const int base = tid * 8;
    int h[8];
    int sum = 0;
#pragma unroll
    for (int j = 0; j < 8; ++j) { h[j] = g_hard[b * LL + base + j]; sum += h[j]; }
    ts[tid] = sum;
    __syncthreads();
    for (int off = 1; off < 256; off <<= 1) {
        int v = (tid >= off) ? ts[tid - off] : 0;
        __syncthreads();
        ts[tid] += v;
        __syncthreads();
    }
    int run = ts[tid] - sum;
#pragma unroll
    for (int j = 0; j < 8; ++j) {
        e_sh[base + j] = run;
        g_cum[b * LL + base + j] = run + h[j];
        run += h[j];
    }
    __syncthreads();
#pragma unroll
    for (int j = 0; j < 8; ++j) {
        const int l = base + j;
        const int el = e_sh[l];
        if (l == 0 || e_sh[l - 1] != el) g_start[b * 2050 + el] = l;
    }
    if (tid == 255) {
        const int ns = e_sh[LL - 1] + 1;
        g_nseg[b] = ns;
        g_start[b * 2050 + ns] = LL;
    }
}

// ---------------------------------------------------------------------
// Kernel 4: shortened = [null_group ; segment means ; zeros]
// ---------------------------------------------------------------------
__global__ void shortened_kernel(const float* __restrict__ x,
                                 const float* __restrict__ null_group,
                                 float* __restrict__ outS) {
    const int b = blockIdx.y;
    const int srow = blockIdx.x;
    const int tid = threadIdx.x;
    float4* op = (float4*)(outS + ((size_t)b * SROWS + srow) * DD) + tid;

    if (srow == 0) { *op = ((const float4*)null_group)[tid]; return; }
    const int s = srow - 1;
    if (s >= g_nseg[b]) { *op = make_float4(0.f, 0.f, 0.f, 0.f); return; }

    const int l0 = g_start[b * 2050 + s];
    const int l1 = g_start[b * 2050 + s + 1];
    float4 acc = make_float4(0.f, 0.f, 0.f, 0.f);
    const float4* xp = (const float4*)(x + ((size_t)b * LL + l0) * DD) + tid;
    for (int l = l0; l < l1; ++l) {
        float4 v = *xp;
        acc.x += v.x; acc.y += v.y; acc.z += v.z; acc.w += v.w;
        xp += DD / 4;
    }
    const float inv = 1.0f / ((float)(l1 - l0) + 1e-9f);
    acc.x *= inv; acc.y *= inv; acc.z *= inv; acc.w *= inv;
    *op = acc;
}

// ---------------------------------------------------------------------
// Kernel 5: upsampled[b,l,:] = shortened[b, cumsum(l), :]
// ---------------------------------------------------------------------
__global__ void upsample_kernel(const float* __restrict__ outS,
                                float* __restrict__ outU) {
    const int b = blockIdx.y;
    const int l = blockIdx.x;
    const int tid = threadIdx.x;
    const int c = g_cum[b * LL + l];
    const float4* sp = (const float4*)(outS + ((size_t)b * SROWS + c) * DD) + tid;
    float4* up = (float4*)(outU + ((size_t)b * LL + l) * DD) + tid;
    *up = *sp;
}

// ---------------------------------------------------------------------
// Kernel 6: binomial consistency loss (scalar)
// ---------------------------------------------------------------------
__global__ void loss_kernel(float* __restrict__ outLoss) {
    if (threadIdx.x == 0) {
        const double Lf = 2048.0;
        const double lgL = lgamma(2049.0);
        const double lp = log(0.25);
        const double l1p = log(0.75);
        double s = 0.0;
        for (int b = 0; b < BB; ++b) {
            double k = (double)g_cum[b * LL + LL - 1];
            double logp = lgL - lgamma(k + 1.0) - lgamma(Lf - k + 1.0)
                        + k * lp + (Lf - k) * l1p;
            s += logp;
        }
        outLoss[0] = (float)(-(s / 8.0) / 2048.0);
    }
}

// ---------------------------------------------------------------------
extern "C" void kernel_launch(void* const* d_in, const int* in_sizes, int n_in,
                              void* d_out, int out_size) {
    (void)in_sizes; (void)n_in; (void)out_size;

    const float* x          = (const float*)d_in[0];
    const float* noise      = (const float*)d_in[1];
    const float* W1         = (const float*)d_in[2];
    const float* b1         = (const float*)d_in[3];
    const float* W2         = (const float*)d_in[4];
    const float* b2         = (const float*)d_in[5];
    const float* null_group = (const float*)d_in[6];

    float* out  = (float*)d_out;
    float* outS = out;                                     // [8, 2049, 1024]
    float* outU = outS + (size_t)BB * SROWS * DD;          // [8, 2048, 1024]
    float* outL = outU + (size_t)BB * LL * DD;             // scalar

    cudaFuncSetAttribute(mma_logits_kernel,
                         cudaFuncAttributeMaxDynamicSharedMemorySize, GEMM_SMEM);

    conv_x_kernel<<<(TOK * DD) / 1024, 256>>>(x);
    transpose_kernel<<<dim3(DD / 32, DD / 32), dim3(32, 8)>>>(W1);
    mma_logits_kernel<<<dim3(TOK / 128, DD / 128), 256, GEMM_SMEM>>>(b1, W2);
    boundary_kernel<<<TOK / 256, 256>>>(noise, b2);
    fixup_kernel<<<128, 256>>>(x, W1, b1, W2, b2, noise);
    scan_kernel<<<BB, 256>>>();
    shortened_kernel<<<dim3(SROWS, BB), 256>>>(x, null_group, outS);
    upsample_kernel<<<dim3(LL, BB), 256>>>(outS, outU);
    loss_kernel<<<1, 32>>>(outL);
}

// round 15
// speedup vs baseline: 2.3312x; 1.0443x over previous
#include <cuda_runtime.h>
#include <cuda_fp16.h>
#include <stdint.h>
#include <math.h>

// Problem constants
#define BB   8
#define LL   2048
#define DD   1024
#define TOK  (BB*LL)            // 16384
#define SROWS 2049              // S_max + 1
#define MARGIN 8e-3f

// ---------------- scratch (no allocations allowed) ----------------
__device__ __half g_xh[(size_t)TOK * DD];   // x in fp16 (32MB)
__device__ __half g_wth[DD * DD];           // W1^T in fp16 (2MB)
__device__ float g_partial[8 * TOK];   // per col-group partial logits
__device__ int   g_hard[TOK];          // hard boundary 0/1
__device__ int   g_cum[TOK];           // inclusive cumsum of hard
__device__ int   g_start[BB * 2050];   // segment start indices (exclusive prefix)
__device__ int   g_ustart[BB * 2050];  // first token with inclusive cum == v
__device__ int   g_nseg[BB];           // number of non-empty segments per row
__device__ int   g_fixtok[TOK];        // marginal tokens to recompute exactly
__device__ int   g_fixcnt;

// ====================== PTX helpers ======================
__device__ __forceinline__ uint32_t cvta_smem(const void* p) {
    uint32_t a;
    asm("{ .reg .u64 t; cvta.to.shared.u64 t, %1; cvt.u32.u64 %0, t; }"
        : "=r"(a) : "l"(p));
    return a;
}
__device__ __forceinline__ void cp16(uint32_t dst, const void* src) {
    asm volatile("cp.async.cg.shared.global [%0], [%1], 16;"
                 :: "r"(dst), "l"(src) : "memory");
}
__device__ __forceinline__ void ldm_x4(uint32_t* r, uint32_t a) {
    asm volatile("ldmatrix.sync.aligned.m8n8.x4.shared.b16 {%0,%1,%2,%3}, [%4];"
                 : "=r"(r[0]), "=r"(r[1]), "=r"(r[2]), "=r"(r[3]) : "r"(a));
}
__device__ __forceinline__ void mma16816(float* c, const uint32_t* a,
                                         uint32_t b0, uint32_t b1) {
    asm volatile(
        "mma.sync.aligned.m16n8k16.row.col.f32.f16.f16.f32 "
        "{%0,%1,%2,%3}, {%4,%5,%6,%7}, {%8,%9}, {%0,%1,%2,%3};"
        : "+f"(c[0]), "+f"(c[1]), "+f"(c[2]), "+f"(c[3])
        : "r"(a[0]), "r"(a[1]), "r"(a[2]), "r"(a[3]), "r"(b0), "r"(b1));
}

// ---------------------------------------------------------------------
// Kernel 0a: convert x to fp16; zero fixup counter
// ---------------------------------------------------------------------
__global__ void conv_x_kernel(const float* __restrict__ x) {
    const size_t i = ((size_t)blockIdx.x * 256 + threadIdx.x) * 4;
    float4 v = *(const float4*)(x + i);
    __half2* p = (__half2*)(g_xh + i);
    p[0] = __floats2half2_rn(v.x, v.y);
    p[1] = __floats2half2_rn(v.z, v.w);
    if (blockIdx.x == 0 && threadIdx.x == 0) g_fixcnt = 0;
}

// ---------------------------------------------------------------------
// Kernel 0b: W1^T in fp16:  wth[n][k] = (half)W1[k][n]
// ---------------------------------------------------------------------
__global__ void transpose_kernel(const float* __restrict__ W1) {
    __shared__ float t[32][33];
    const int bx = blockIdx.x * 32;   // n base
    const int by = blockIdx.y * 32;   // k base
    const int tx = threadIdx.x, ty = threadIdx.y;
#pragma unroll
    for (int i = 0; i < 32; i += 8)
        t[ty + i][tx] = W1[(size_t)(by + ty + i) * DD + bx + tx];
    __syncthreads();
#pragma unroll
    for (int i = 0; i < 32; i += 8) {
        float v = t[tx][ty + i];               // = W1[by+tx][bx+ty+i]
        g_wth[(size_t)(bx + ty + i) * DD + by + tx] = __float2half_rn(v);
    }
}

// ---------------------------------------------------------------------
// Kernel 1: HMMA fp16 GEMM with fused relu+W2 epilogue.
// grid (128 token tiles, 8 col groups), 256 threads (8 warps, 2x4).
// CTA tile M=128, N=128, K chunks of 64; 3-stage cp.async pipeline.
// ---------------------------------------------------------------------
#define KC 64
#define STAGE_BYTES 32768          // A tile 16KB + B tile 16KB
#define NSTAGE 3
#define GEMM_SMEM (4096 + NSTAGE * STAGE_BYTES)

__global__ __launch_bounds__(256, 2)
void mma_logits_kernel(const float* __restrict__ b1g, const float* __restrict__ w2g) {
    extern __shared__ char smem[];
    float* b1s = (float*)smem;                 // 512B
    float* w2s = (float*)(smem + 512);         // 512B
    float* red = (float*)(smem + 1024);        // 4*128 floats = 2KB
    const uint32_t tiles_u = cvta_smem(smem + 4096);

    const int tid = threadIdx.x;
    const int wid = tid >> 5, lane = tid & 31;
    const int t0 = blockIdx.x * 128;
    const int j0 = blockIdx.y * 128;
    const int warp_m = wid & 1;    // 0..1  (64 rows each)
    const int warp_n = wid >> 1;   // 0..3  (32 cols each)

    if (tid < 128) { b1s[tid] = b1g[j0 + tid]; w2s[tid] = w2g[j0 + tid]; }

    // cp.async stage loader: 1024 16B-chunks per tile (A then B), XOR swizzle
    auto load_stage = [&](int c, int st) {
        const uint32_t base = tiles_u + st * STAGE_BYTES;
        const __half* aS = g_xh + (size_t)t0 * DD + c * KC;
        const __half* bS = g_wth + (size_t)j0 * DD + c * KC;
#pragma unroll
        for (int it = 0; it < 4; ++it) {
            const int idx = tid + it * 256;          // 0..1023
            const int row = idx >> 3, ch = idx & 7;  // 128 rows x 8 chunks
            const uint32_t off = (uint32_t)(row * 128 + ((ch ^ (row & 7)) << 4));
            cp16(base + off,         aS + (size_t)row * DD + ch * 8);
            cp16(base + 16384 + off, bS + (size_t)row * DD + ch * 8);
        }
        asm volatile("cp.async.commit_group;" ::: "memory");
    };

    float acc[4][4][4];
#pragma unroll
    for (int mt = 0; mt < 4; ++mt)
#pragma unroll
        for (int nt = 0; nt < 4; ++nt)
#pragma unroll
            for (int q = 0; q < 4; ++q) acc[mt][nt][q] = 0.0f;

    load_stage(0, 0);
    load_stage(1, 1);

    for (int c = 0; c < 16; ++c) {
        const int st = c % NSTAGE;
        if (c < 15) asm volatile("cp.async.wait_group 1;" ::: "memory");
        else        asm volatile("cp.async.wait_group 0;" ::: "memory");
        __syncthreads();
        if (c + 2 < 16) load_stage(c + 2, (c + 2) % NSTAGE);

        const uint32_t aBase = tiles_u + st * STAGE_BYTES;
        const uint32_t bBase = aBase + 16384;

#pragma unroll
        for (int ks = 0; ks < 4; ++ks) {
            uint32_t af[4][4];
#pragma unroll
            for (int mt = 0; mt < 4; ++mt) {
                const int row = warp_m * 64 + mt * 16 + (lane & 15);
                const int ch = ks * 2 + (lane >> 4);
                ldm_x4(af[mt], aBase + row * 128 + (((ch ^ (row & 7)) << 4)));
            }
#pragma unroll
            for (int np = 0; np < 2; ++np) {     // covers n-tiles 2np, 2np+1
                const int grp = lane >> 3;
                const int n = warp_n * 32 + np * 16 + (grp & 1) * 8 + (lane & 7);
                const int ch = ks * 2 + (grp >> 1);
                uint32_t bf[4];
                ldm_x4(bf, bBase + n * 128 + (((ch ^ (n & 7)) << 4)));
#pragma unroll
                for (int mt = 0; mt < 4; ++mt) {
                    mma16816(acc[mt][np * 2],     af[mt], bf[0], bf[2]);
                    mma16816(acc[mt][np * 2 + 1], af[mt], bf[1], bf[3]);
                }
            }
        }
    }

    // ---- epilogue: lg[row] = sum_j relu(h + b1) * W2 over this 128-col group ----
    float accr[4][2];
#pragma unroll
    for (int mt = 0; mt < 4; ++mt) { accr[mt][0] = 0.f; accr[mt][1] = 0.f; }
#pragma unroll
    for (int nt = 0; nt < 4; ++nt) {
        const int cb = warp_n * 32 + nt * 8 + 2 * (lane & 3);
        const float w0 = w2s[cb], w1 = w2s[cb + 1];
        const float bb0 = b1s[cb], bb1 = b1s[cb + 1];
#pragma unroll
        for (int mt = 0; mt < 4; ++mt) {
            accr[mt][0] += fmaxf(acc[mt][nt][0] + bb0, 0.f) * w0
                         + fmaxf(acc[mt][nt][1] + bb1, 0.f) * w1;
            accr[mt][1] += fmaxf(acc[mt][nt][2] + bb0, 0.f) * w0
                         + fmaxf(acc[mt][nt][3] + bb1, 0.f) * w1;
        }
    }
    __syncthreads();   // done with tiles; red reuse safe
#pragma unroll
    for (int mt = 0; mt < 4; ++mt) {
#pragma unroll
        for (int h = 0; h < 2; ++h) {
            float v = accr[mt][h];
            v += __shfl_xor_sync(0xFFFFFFFFu, v, 1);
            v += __shfl_xor_sync(0xFFFFFFFFu, v, 2);
            if ((lane & 3) == 0)
                red[warp_n * 128 + warp_m * 64 + mt * 16 + (lane >> 2) + h * 8] = v;
        }
    }
    __syncthreads();
    if (tid < 128) {
        const float s = red[tid] + red[128 + tid] + red[256 + tid] + red[384 + tid];
        g_partial[(size_t)blockIdx.y * TOK + t0 + tid] = s;
    }
}

// ---------------------------------------------------------------------
// Kernel 2: combine partials + gumbel noise -> hard boundaries (+fix list)
// ---------------------------------------------------------------------
__global__ void boundary_kernel(const float* __restrict__ noise,
                                const float* __restrict__ b2) {
    const int i = blockIdx.x * 256 + threadIdx.x;
    float s = b2[0];
#pragma unroll
    for (int cg = 0; cg < 8; ++cg) s += g_partial[cg * TOK + i];
    float u = noise[i];
    u = fminf(fmaxf(u, 1e-6f), 1.0f - 1e-6f);
    const float z = s + logf(u) - log1pf(-u);
    const float soft = 1.0f / (1.0f + expf(-z));
    g_hard[i] = (soft > 0.5f) ? 1 : 0;
    if (fabsf(z) < MARGIN) {
        const int p = atomicAdd(&g_fixcnt, 1);
        g_fixtok[p] = i;
    }
}

// ---------------------------------------------------------------------
// Kernel 2b: exact fp32 recompute of marginal tokens' logits
// ---------------------------------------------------------------------
__global__ void fixup_kernel(const float* __restrict__ x, const float* __restrict__ W1,
                             const float* __restrict__ b1, const float* __restrict__ W2,
                             const float* __restrict__ b2, const float* __restrict__ noise) {
    __shared__ float xs[DD];
    __shared__ float red[256];
    const int nt = g_fixcnt;
    for (int fi = blockIdx.x; fi < nt; fi += gridDim.x) {
        const int t = g_fixtok[fi];
        for (int k = threadIdx.x; k < DD; k += 256) xs[k] = x[(size_t)t * DD + k];
        __syncthreads();
        float acc[4] = {0.f, 0.f, 0.f, 0.f};
        for (int k = 0; k < DD; ++k) {
            const float xv = xs[k];
            const float* wr = W1 + (size_t)k * DD;
#pragma unroll
            for (int q = 0; q < 4; ++q) acc[q] += xv * wr[threadIdx.x + q * 256];
        }
        float lg = 0.0f;
#pragma unroll
        for (int q = 0; q < 4; ++q) {
            const int j = threadIdx.x + q * 256;
            lg += fmaxf(acc[q] + b1[j], 0.0f) * W2[j];
        }
        red[threadIdx.x] = lg;
        __syncthreads();
        for (int off = 128; off > 0; off >>= 1) {
            if (threadIdx.x < off) red[threadIdx.x] += red[threadIdx.x + off];
            __syncthreads();
        }
        if (threadIdx.x == 0) {
            const float s = red[0] + b2[0];
            float u = fminf(fmaxf(noise[t], 1e-6f), 1.0f - 1e-6f);
            const float z = s + logf(u) - log1pf(-u);
            const float soft = 1.0f / (1.0f + expf(-z));
            g_hard[t] = (soft > 0.5f) ? 1 : 0;
        }
        __syncthreads();
    }
}

// ---------------------------------------------------------------------
// Kernel 3: per-row prefix scan, segment starts, cum, ustart tables
// ---------------------------------------------------------------------
__global__ void scan_kernel() {
    const int b = blockIdx.x;
    const int tid = threadIdx.x;
    __shared__ int e_sh[LL];
    __shared__ int ts[256];

    // init ustart table to LL (empty ranges)
    for (int v = tid; v < 2050; v += 256) g_ustart[b * 2050 + v] = LL;

    const int base = tid * 8;
    int h[8];
    int sum = 0;
#pragma unroll
    for (int j = 0; j < 8; ++j) { h[j] = g_hard[b * LL + base + j]; sum += h[j]; }
    ts[tid] = sum;
    __syncthreads();
    for (int off = 1; off < 256; off <<= 1) {
        int v = (tid >= off) ? ts[tid - off] : 0;
        __syncthreads();
        ts[tid] += v;
        __syncthreads();
    }
    int run = ts[tid] - sum;
#pragma unroll
    for (int j = 0; j < 8; ++j) {
        e_sh[base + j] = run;
        const int inc = run + h[j];
        g_cum[b * LL + base + j] = inc;
        if (h[j]) g_ustart[b * 2050 + inc] = base + j;  // first (and only) boundary for value inc
        run += h[j];
    }
    __syncthreads();
#pragma unroll
    for (int j = 0; j < 8; ++j) {
        const int l = base + j;
        const int el = e_sh[l];
        if (l == 0 || e_sh[l - 1] != el) g_start[b * 2050 + el] = l;
    }
    if (tid == 0) g_ustart[b * 2050 + 0] = 0;
    if (tid == 255) {
        const int ns = e_sh[LL - 1] + 1;
        g_nseg[b] = ns;
        g_start[b * 2050 + ns] = LL;  // sentinel end
    }
}

// ---------------------------------------------------------------------
// Kernel 4 (fused): per (b, v):  outS[b][v] = null/mean/zero,
// and outU[b][l] = outS[b][v] for all l with cum[l] == v  (contiguous range)
// ---------------------------------------------------------------------
__global__ void segout_kernel(const float* __restrict__ x,
                              const float* __restrict__ null_group,
                              float* __restrict__ outS,
                              float* __restrict__ outU) {
    const int b = blockIdx.y;
    const int v = blockIdx.x;       // 0..2048
    const int tid = threadIdx.x;

    float4 val;
    if (v == 0) {
        val = ((const float4*)null_group)[tid];
    } else {
        const int s = v - 1;
        if (s < g_nseg[b]) {
            const int l0 = g_start[b * 2050 + s];
            const int l1 = g_start[b * 2050 + s + 1];
            float4 acc = make_float4(0.f, 0.f, 0.f, 0.f);
            const float4* xp = (const float4*)(x + ((size_t)b * LL + l0) * DD) + tid;
            for (int l = l0; l < l1; ++l) {
                float4 w = *xp;
                acc.x += w.x; acc.y += w.y; acc.z += w.z; acc.w += w.w;
                xp += DD / 4;
            }
            const float inv = 1.0f / ((float)(l1 - l0) + 1e-9f);
            acc.x *= inv; acc.y *= inv; acc.z *= inv; acc.w *= inv;
            val = acc;
        } else {
            val = make_float4(0.f, 0.f, 0.f, 0.f);
        }
    }

    ((float4*)(outS + ((size_t)b * SROWS + v) * DD))[tid] = val;

    const int u0 = g_ustart[b * 2050 + v];
    const int u1 = g_ustart[b * 2050 + v + 1];
    float4* up = (float4*)(outU + ((size_t)b * LL + u0) * DD) + tid;
    for (int l = u0; l < u1; ++l) {
        *up = val;
        up += DD / 4;
    }
}

// ---------------------------------------------------------------------
// Kernel 6: binomial consistency loss (scalar)
// ---------------------------------------------------------------------
__global__ void loss_kernel(float* __restrict__ outLoss) {
    if (threadIdx.x == 0) {
        const double Lf = 2048.0;
        const double lgL = lgamma(2049.0);
        const double lp = log(0.25);
        const double l1p = log(0.75);
        double s = 0.0;
        for (int b = 0; b < BB; ++b) {
            double k = (double)g_cum[b * LL + LL - 1];
            double logp = lgL - lgamma(k + 1.0) - lgamma(Lf - k + 1.0)
                        + k * lp + (Lf - k) * l1p;
            s += logp;
        }
        outLoss[0] = (float)(-(s / 8.0) / 2048.0);
    }
}

// ---------------------------------------------------------------------
extern "C" void kernel_launch(void* const* d_in, const int* in_sizes, int n_in,
                              void* d_out, int out_size) {
    (void)in_sizes; (void)n_in; (void)out_size;

    const float* x          = (const float*)d_in[0];
    const float* noise      = (const float*)d_in[1];
    const float* W1         = (const float*)d_in[2];
    const float* b1         = (const float*)d_in[3];
    const float* W2         = (const float*)d_in[4];
    const float* b2         = (const float*)d_in[5];
    const float* null_group = (const float*)d_in[6];

    float* out  = (float*)d_out;
    float* outS = out;                                     // [8, 2049, 1024]
    float* outU = outS + (size_t)BB * SROWS * DD;          // [8, 2048, 1024]
    float* outL = outU + (size_t)BB * LL * DD;             // scalar

    cudaFuncSetAttribute(mma_logits_kernel,
                         cudaFuncAttributeMaxDynamicSharedMemorySize, GEMM_SMEM);

    conv_x_kernel<<<(TOK * DD) / 1024, 256>>>(x);
    transpose_kernel<<<dim3(DD / 32, DD / 32), dim3(32, 8)>>>(W1);
    mma_logits_kernel<<<dim3(TOK / 128, DD / 128), 256, GEMM_SMEM>>>(b1, W2);
    boundary_kernel<<<TOK / 256, 256>>>(noise, b2);
    fixup_kernel<<<128, 256>>>(x, W1, b1, W2, b2, noise);
    scan_kernel<<<BB, 256>>>();
    segout_kernel<<<dim3(SROWS, BB), 256>>>(x, null_group, outS, outU);
    loss_kernel<<<1, 32>>>(outL);
}